// round 17
// baseline (speedup 1.0000x reference)
#include <cuda_runtime.h>

#define B_ 16
#define ORDER_ 2
#define N_ 512
#define D_ 128
#define H_ 8
#define DH_ 16
#define NBIC 64   // B*ORDER*2 (b,i,c) combos

// ---------------- scratch (device globals; no allocations) ----------------
__device__ __align__(16) float g_xp  [NBIC * N_ * D_];     // projected features (+pb)
__device__ __align__(16) float g_src2[NBIC * N_ * H_ * 2]; // {exp(ssrc), exp(.2 ssrc)}
__device__ __align__(16) float g_dst2[NBIC * N_ * H_ * 2]; // {exp(sdst), exp(.2 sdst)}
__device__ __align__(16) unsigned int g_mask[NBIC * N_ * (N_ / 32)]; // 1 bit/edge
__device__ __align__(16) float g_att [NBIC * N_ * D_];     // per-conv GAT output

#define TF32_TRUNC 0xFFFFE000u
#define ONE_BITS   0x3F800000u

// ---------------- helpers ----------------
__device__ __forceinline__ void cpa16(unsigned int s, const void* g) {
    asm volatile("cp.async.cg.shared.global [%0], [%1], 16;" :: "r"(s), "l"(g) : "memory");
}
__device__ __forceinline__ void cpa8(unsigned int s, const void* g) {
    asm volatile("cp.async.ca.shared.global [%0], [%1], 8;" :: "r"(s), "l"(g) : "memory");
}
__device__ __forceinline__ void cpa_commit() {
    asm volatile("cp.async.commit_group;" ::: "memory");
}
__device__ __forceinline__ void cpa_wait0() {
    asm volatile("cp.async.wait_group 0;" ::: "memory");
}
__device__ __forceinline__ void mma_tf32(float* c,
    unsigned int a0, unsigned int a1, unsigned int a2, unsigned int a3,
    unsigned int b0, unsigned int b1) {
    asm("mma.sync.aligned.m16n8k8.row.col.f32.tf32.tf32.f32 "
        "{%0,%1,%2,%3}, {%4,%5,%6,%7}, {%8,%9}, {%0,%1,%2,%3};"
        : "+f"(c[0]), "+f"(c[1]), "+f"(c[2]), "+f"(c[3])
        : "r"(a0), "r"(a1), "r"(a2), "r"(a3), "r"(b0), "r"(b1));
}
__device__ __forceinline__ unsigned int smem_u32(const void* p) {
    unsigned int r;
    asm("{.reg .u64 t; cvta.to.shared.u64 t, %1; cvt.u32.u64 %0, t;}" : "=r"(r) : "l"(p));
    return r;
}
// truncation-based tf32 hi/lo split (LOP3 only, no F2FP)
__device__ __forceinline__ void tf32_split(float v, unsigned int& hi, unsigned int& lo) {
    hi = __float_as_uint(v) & TF32_TRUNC;
    lo = __float_as_uint(v - __uint_as_float(hi)) & TF32_TRUNC;
}

// ============================================================================
// Kernel 0: bit-packed edge masks via ballot.
// ============================================================================
__global__ __launch_bounds__(256) void mask_kernel(const int* __restrict__ A) {
    int gid  = blockIdx.x * 256 + threadIdx.x;
    int lane = gid & 31;
    int wlin = gid >> 5;
    int bi   = wlin >> 13;
    int rr   = wlin & 8191;
    int s    = rr >> 4, w = rr & 15;
    int a = A[((size_t)(bi * N_ + s)) * N_ + w * 32 + lane];
    unsigned int m0 = __ballot_sync(0xffffffffu, a == 4 || a == 2);
    unsigned int m1 = __ballot_sync(0xffffffffu, a == 4 || a == 3);
    if (lane == 0) g_mask[((size_t)(bi * 2 + 0) * N_ + s) * 16 + w] = m0;
    if (lane == 1) g_mask[((size_t)(bi * 2 + 1) * N_ + s) * 16 + w] = m1;
}

// ============================================================================
// Kernel 1: projection xp = x @ W^T + pb via 3xTF32 mma (fp32-accurate).
// grid (8 row-tiles of 64, 64 bic), 256 thr (8 warps = 2m x 4n, 32x32 tiles).
// ============================================================================
#define PJ_X_F (64 * 36)
#define PJ_STAGE_F (PJ_X_F + 128 * 36)     // 6912 floats
#define PJ_SMEM_BYTES (2 * PJ_STAGE_F * 4) // 55296

__global__ __launch_bounds__(256, 2) void proj_kernel(
    const float* __restrict__ x, const float* __restrict__ W, const float* __restrict__ pb)
{
    extern __shared__ __align__(16) float smem[];
    const int bic = blockIdx.y;
    const int mt  = blockIdx.x;
    const int c    = bic & 1;
    const int bi   = bic >> 1;
    const int iord = bi & 1;
    const int tid  = threadIdx.x;
    const int lane = tid & 31, warp = tid >> 5;
    const int wm = warp & 1, wn = warp >> 1;
    const int g  = lane >> 2, tg = lane & 3;

    const unsigned int sbase = smem_u32(smem);
    const float* xb = x + ((size_t)bi * N_ + mt * 64) * D_;
    const float* Wb = W + (size_t)(iord * 2 + c) * D_ * D_;

    auto issue = [&](int kc, int buf) {
        const unsigned int bb = sbase + (unsigned)(buf * PJ_STAGE_F * 4);
#pragma unroll
        for (int j = 0; j < 2; j++) {          // x: 64 rows
            int idx = tid + j * 256;
            int r = idx >> 3, kq = idx & 7;
            cpa16(bb + (unsigned)((r * 36 + kq * 4) * 4),
                  xb + (size_t)r * D_ + kc * 32 + kq * 4);
        }
#pragma unroll
        for (int j = 0; j < 4; j++) {          // W: 128 rows
            int idx = tid + j * 256;
            int r = idx >> 3, kq = idx & 7;
            cpa16(bb + (unsigned)((PJ_X_F + r * 36 + kq * 4) * 4),
                  Wb + (size_t)r * D_ + kc * 32 + kq * 4);
        }
        cpa_commit();
    };

    float c_[2][4][4];
#pragma unroll
    for (int f = 0; f < 2; f++)
#pragma unroll
        for (int n = 0; n < 4; n++)
#pragma unroll
            for (int k = 0; k < 4; k++) c_[f][n][k] = 0.0f;

    issue(0, 0);

#pragma unroll 1
    for (int kc = 0; kc < 4; kc++) {
        cpa_wait0();
        __syncthreads();
        if (kc < 3) issue(kc + 1, (kc + 1) & 1);
        const float* xs = smem + (kc & 1) * PJ_STAGE_F;
        const float* ws = xs + PJ_X_F;

#pragma unroll
        for (int k8 = 0; k8 < 4; k8++) {
            const int k = k8 * 8;
            unsigned int ah[2][4], al[2][4];
#pragma unroll
            for (int f = 0; f < 2; f++) {
                const int r0 = wm * 32 + f * 16 + g;
                tf32_split(xs[(r0)     * 36 + k + tg],     ah[f][0], al[f][0]);
                tf32_split(xs[(r0 + 8) * 36 + k + tg],     ah[f][1], al[f][1]);
                tf32_split(xs[(r0)     * 36 + k + tg + 4], ah[f][2], al[f][2]);
                tf32_split(xs[(r0 + 8) * 36 + k + tg + 4], ah[f][3], al[f][3]);
            }
#pragma unroll
            for (int n = 0; n < 4; n++) {
                const int dr = wn * 32 + n * 8 + g;
                unsigned int bh0, bl0, bh1, bl1;
                tf32_split(ws[dr * 36 + k + tg],     bh0, bl0);
                tf32_split(ws[dr * 36 + k + tg + 4], bh1, bl1);
#pragma unroll
                for (int f = 0; f < 2; f++) {
                    mma_tf32(c_[f][n], ah[f][0], ah[f][1], ah[f][2], ah[f][3], bh0, bh1);
                    mma_tf32(c_[f][n], ah[f][0], ah[f][1], ah[f][2], ah[f][3], bl0, bl1);
                    mma_tf32(c_[f][n], al[f][0], al[f][1], al[f][2], al[f][3], bh0, bh1);
                }
            }
        }
    }

    // epilogue: + pb, store xp
    const float* pbp = pb + (iord * 2 + c) * D_;
#pragma unroll
    for (int n = 0; n < 4; n++) {
        const int dout = wn * 32 + n * 8 + 2 * tg;
        float2 pbv = *(const float2*)(pbp + dout);
#pragma unroll
        for (int f = 0; f < 2; f++) {
            const int r0 = mt * 64 + wm * 32 + f * 16 + g;
            float2 o0, o1;
            o0.x = c_[f][n][0] + pbv.x; o0.y = c_[f][n][1] + pbv.y;
            o1.x = c_[f][n][2] + pbv.x; o1.y = c_[f][n][3] + pbv.y;
            *(float2*)(g_xp + ((size_t)bic * N_ + r0)     * D_ + dout) = o0;
            *(float2*)(g_xp + ((size_t)bic * N_ + r0 + 8) * D_ + dout) = o1;
        }
    }
}

// ============================================================================
// Kernel 1b: per-(node,head) scores + exp forms from g_xp.
// ============================================================================
__global__ __launch_bounds__(256) void score_kernel(
    const float* __restrict__ asrc, const float* __restrict__ adst)
{
    int gid = blockIdx.x * 256 + threadIdx.x;   // 64*512*8
    int h = gid & 7;
    int n = (gid >> 3) & 511;
    int bic = gid >> 12;
    int c = bic & 1, iord = (bic >> 1) & 1;
    const float* xph = g_xp + ((size_t)bic * N_ + n) * D_ + h * DH_;
    const float* av = asrc + ((iord * 2 + c) * H_ + h) * DH_;
    const float* dv = adst + ((iord * 2 + c) * H_ + h) * DH_;
    float ps = 0.0f, pd = 0.0f;
#pragma unroll
    for (int j = 0; j < 4; j++) {
        float4 xv = *(const float4*)(xph + j * 4);
        float4 a4 = *(const float4*)(av + j * 4);
        float4 d4 = *(const float4*)(dv + j * 4);
        ps += xv.x * a4.x + xv.y * a4.y + xv.z * a4.z + xv.w * a4.w;
        pd += xv.x * d4.x + xv.y * d4.y + xv.z * d4.z + xv.w * d4.w;
    }
    size_t o = ((size_t)bic * N_ + n) * H_ + h;
    *(float2*)(g_src2 + o * 2) = make_float2(__expf(ps), __expf(0.2f * ps));
    *(float2*)(g_dst2 + o * 2) = make_float2(__expf(pd), __expf(0.2f * pd));
}

// ============================================================================
// Kernel 2: attention via mma tf32; 64-dst tiles; 3 blocks/SM (85 regs);
// dst-side exp pairs read from smem per use (frees 16 regs vs hoisting).
// grid (8 dtiles x 64 bic), 256 thr, warp = head; 4 m-tiles x 2 n-frags, K=512.
// ============================================================================
#define TS 32
#define SD_F 1152
#define BUF_F 4992
#define ATT_SMEM_BYTES ((SD_F + 2 * BUF_F) * 4)

__global__ __launch_bounds__(256, 3) void att_kernel(const float* __restrict__ bias)
{
    extern __shared__ __align__(16) float smem[];
    const int bic  = blockIdx.y;
    const int tile = blockIdx.x;
    const int c    = bic & 1;
    const int bi   = bic >> 1;
    const int iord = bi & 1;
    const int tid  = threadIdx.x;
    const int lane = tid & 31;
    const int h    = tid >> 5;           // warp = head
    const int row  = lane >> 2;          // mma group id
    const int qid  = lane & 3;

    const unsigned int sbase = smem_u32(smem);
    const float* xp    = g_xp   + (size_t)bic * N_ * D_;
    const float* src2p = g_src2 + (size_t)bic * N_ * H_ * 2;
    const float* dst2p = g_dst2 + (size_t)bic * N_ * H_ * 2;
    const unsigned int* mgp = g_mask + (size_t)bic * N_ * 16 + tile * 2;

    const int xs_s = tid >> 5, xs_fq = tid & 31;
    const int ss_s = tid >> 3, ss_h = tid & 7;

    auto issue = [&](int t, int buf) {
        const int s0 = t * TS;
        const unsigned int b = sbase + (SD_F + buf * BUF_F) * 4;
#pragma unroll
        for (int k = 0; k < 4; k++) {
            int s = xs_s + k * 8;
            cpa16(b + (unsigned)(s * 544 + xs_fq * 16),
                  xp + (size_t)(s0 + s) * D_ + xs_fq * 4);
        }
        cpa8(b + 17408u + (unsigned)((ss_s * 9 + ss_h) * 8),
             src2p + ((size_t)(s0 + ss_s) * H_ + ss_h) * 2);
        if (tid < 32)
            cpa8(b + 19712u + (unsigned)(tid * 8), mgp + (size_t)(s0 + tid) * 16);
        cpa_commit();
    };

    // preload sd (64 dst x 8 h float2) together with first tile
#pragma unroll
    for (int k = 0; k < 2; k++) {
        int idx = tid + k * 256;
        int d = idx >> 3, hh = idx & 7;
        cpa8(sbase + (unsigned)((d * 9 + hh) * 8),
             dst2p + ((size_t)(tile * 64 + d) * H_ + hh) * 2);
    }
    issue(0, 0);

    float c_[4][2][4];
    float z_[4][2];
#pragma unroll
    for (int m = 0; m < 4; m++) {
        z_[m][0] = 0.0f; z_[m][1] = 0.0f;
#pragma unroll
        for (int j = 0; j < 2; j++)
#pragma unroll
            for (int k = 0; k < 4; k++) c_[m][j][k] = 0.0f;
    }

#pragma unroll 1
    for (int t = 0; t < N_ / TS; t++) {
        const int p = t & 1;
        cpa_wait0();
        __syncthreads();
        if (t < N_ / TS - 1) issue(t + 1, 1 - p);

        const float* xhp = smem + SD_F + p * BUF_F;
        const float* ssp = xhp + 4352;
        const unsigned int* mkp = (const unsigned int*)(ssp + 576);

#pragma unroll
        for (int kc = 0; kc < 4; kc++) {
            const int s_lo = kc * 8 + qid;
            const int s_hi = s_lo + 4;
            float2 pA = *(const float2*)(ssp + (s_lo * 9 + h) * 2);
            float2 pB = *(const float2*)(ssp + (s_hi * 9 + h) * 2);
            uint2 mA2 = *(const uint2*)(mkp + s_lo * 2);
            uint2 mB2 = *(const uint2*)(mkp + s_hi * 2);
            // pre-shift mask words by this thread's row (bits at 0/8/16/24)
            const unsigned int uA0 = mA2.x >> row, uA1 = mA2.y >> row;
            const unsigned int uB0 = mB2.x >> row, uB1 = mB2.y >> row;
            unsigned int b0[2], b1[2];
#pragma unroll
            for (int j = 0; j < 2; j++) {
                int f = h * 16 + j * 8 + row;
                b0[j] = __float_as_uint(xhp[s_lo * 136 + f]) & TF32_TRUNC;
                b1[j] = __float_as_uint(xhp[s_hi * 136 + f]) & TF32_TRUNC;
            }
#pragma unroll
            for (int m = 0; m < 4; m++) {
                // dst-side exp pairs from smem (loop-invariant but cheap broadcast LDS)
                float2 qAv = *(const float2*)(smem + ((m * 16 + row) * 9 + h) * 2);
                float2 qBv = *(const float2*)(smem + ((m * 16 + row + 8) * 9 + h) * 2);
                const unsigned int wA = (m < 2) ? uA0 : uA1;
                const unsigned int wB = (m < 2) ? uB0 : uB1;
                const unsigned int bitLo = 1u   << ((m & 1) << 4);
                const unsigned int bitHi = 256u << ((m & 1) << 4);
                float e00 = fmaxf(pA.x * qAv.x, pA.y * qAv.y);
                float e10 = fmaxf(pA.x * qBv.x, pA.y * qBv.y);
                float e01 = fmaxf(pB.x * qAv.x, pB.y * qAv.y);
                float e11 = fmaxf(pB.x * qBv.x, pB.y * qBv.y);
                unsigned int a0 = (wA & bitLo) ? (__float_as_uint(e00) & TF32_TRUNC) : ONE_BITS;
                unsigned int a1 = (wA & bitHi) ? (__float_as_uint(e10) & TF32_TRUNC) : ONE_BITS;
                unsigned int a2 = (wB & bitLo) ? (__float_as_uint(e01) & TF32_TRUNC) : ONE_BITS;
                unsigned int a3 = (wB & bitHi) ? (__float_as_uint(e11) & TF32_TRUNC) : ONE_BITS;
                // Z uses the SAME truncated weights as the numerator mma
                z_[m][0] += __uint_as_float(a0) + __uint_as_float(a2);
                z_[m][1] += __uint_as_float(a1) + __uint_as_float(a3);
                mma_tf32(c_[m][0], a0, a1, a2, a3, b0[0], b1[0]);
                mma_tf32(c_[m][1], a0, a1, a2, a3, b0[1], b1[1]);
            }
        }
    }

    // epilogue: reduce Z over quad, /Z, +xp, +bias, store
    const float* biasp = bias + (iord * 2 + c) * D_;
#pragma unroll
    for (int m = 0; m < 4; m++) {
        float z0 = z_[m][0];
        z0 += __shfl_xor_sync(0xffffffffu, z0, 1);
        z0 += __shfl_xor_sync(0xffffffffu, z0, 2);
        float z1 = z_[m][1];
        z1 += __shfl_xor_sync(0xffffffffu, z1, 1);
        z1 += __shfl_xor_sync(0xffffffffu, z1, 2);
        const float i0 = 1.0f / z0, i1 = 1.0f / z1;
        const int dA = tile * 64 + m * 16 + row;
        const int dB = dA + 8;
#pragma unroll
        for (int j = 0; j < 2; j++) {
            const int f = h * 16 + j * 8 + 2 * qid;
            float2 xA = *(const float2*)(xp + (size_t)dA * D_ + f);
            float2 xB = *(const float2*)(xp + (size_t)dB * D_ + f);
            float2 bb = *(const float2*)(biasp + f);
            float2 oA, oB;
            oA.x = c_[m][j][0] * i0 + xA.x + bb.x;
            oA.y = c_[m][j][1] * i0 + xA.y + bb.y;
            oB.x = c_[m][j][2] * i1 + xB.x + bb.x;
            oB.y = c_[m][j][3] * i1 + xB.y + bb.y;
            *(float2*)(g_att + ((size_t)bic * N_ + dA) * D_ + f) = oA;
            *(float2*)(g_att + ((size_t)bic * N_ + dB) * D_ + f) = oB;
        }
    }
}

// ============================================================================
// Kernel 3: combine.
// ============================================================================
__global__ void combine_kernel(float4* __restrict__ out) {
    int gid = blockIdx.x * blockDim.x + threadIdx.x;
    int b = gid >> 14;
    int r = gid & 16383;
    const float4* a = (const float4*)g_att;
    float4 a00 = a[(size_t)(b * 4 + 0) * 16384 + r];
    float4 a01 = a[(size_t)(b * 4 + 1) * 16384 + r];
    float4 a10 = a[(size_t)(b * 4 + 2) * 16384 + r];
    float4 a11 = a[(size_t)(b * 4 + 3) * 16384 + r];
    float4 h0, h1, o0, o1;
    h0.x = a00.x + a01.x; h0.y = a00.y + a01.y; h0.z = a00.z + a01.z; h0.w = a00.w + a01.w;
    h1.x = a10.x + a11.x; h1.y = a10.y + a11.y; h1.z = a10.z + a11.z; h1.w = a10.w + a11.w;
    float mx = 0.5f * (h0.x + h1.x), my = 0.5f * (h0.y + h1.y);
    float mz = 0.5f * (h0.z + h1.z), mw = 0.5f * (h0.w + h1.w);
    o0.x = h0.x + mx; o0.y = h0.y + my; o0.z = h0.z + mz; o0.w = h0.w + mw;
    o1.x = h1.x + mx; o1.y = h1.y + my; o1.z = h1.z + mz; o1.w = h1.w + mw;
    out[(size_t)(b * 2 + 0) * 16384 + r] = o0;
    out[(size_t)(b * 2 + 1) * 16384 + r] = o1;
}

// ============================================================================
extern "C" void kernel_launch(void* const* d_in, const int* in_sizes, int n_in,
                              void* d_out, int out_size) {
    const float* x    = (const float*)d_in[0];
    const int*   A    = (const int*)  d_in[1];
    const float* W    = (const float*)d_in[2];
    const float* pb   = (const float*)d_in[3];
    const float* asrc = (const float*)d_in[4];
    const float* adst = (const float*)d_in[5];
    const float* bias = (const float*)d_in[6];

    cudaFuncSetAttribute(proj_kernel, cudaFuncAttributeMaxDynamicSharedMemorySize,
                         PJ_SMEM_BYTES);
    cudaFuncSetAttribute(att_kernel, cudaFuncAttributeMaxDynamicSharedMemorySize,
                         ATT_SMEM_BYTES);

    mask_kernel<<<32768, 256>>>(A);
    proj_kernel<<<dim3(8, 64), 256, PJ_SMEM_BYTES>>>(x, W, pb);
    score_kernel<<<1024, 256>>>(asrc, adst);
    att_kernel<<<dim3(8, 64), 256, ATT_SMEM_BYTES>>>(bias);
    combine_kernel<<<1024, 256>>>((float4*)d_out);
}